// round 17
// baseline (speedup 1.0000x reference)
#include <cuda_runtime.h>
#include <cuda_bf16.h>

#define B_    16
#define NPTS  4096
#define QTOT  (2 * B_ * NPTS)     // 131072 queries
#define NB    512                 // x-buckets over [-8, 8)
#define XMIN  (-8.0f)
#define BW    0.03125f
#define INVW  32.0f
#define PTH   512                 // prep threads
#define W     6                   // pass-1 window margin (buckets) = 0.1875
#define P1TH  256
#define P1BLOCKS (QTOT / (P1TH * 2))   // 256 blocks, 2 queries/thread
#define SGTH  256
#define SGBLOCKS 128              // 1024 straggler warps
#define RTH   256
#define RBLOCKS 128               // 128*256*4 = 131072

#define SMEM_PREP (NPTS * (int)sizeof(float4) + (2 * NB + 1) * (int)sizeof(int))

// Scratch (no device allocations allowed)
__device__ float4 g_db[2][B_][NPTS];      // bucket-ordered {x,y,z, 0.5|p|^2}
__device__ int    g_off[2][B_][NB + 1];   // CSR bucket offsets
__device__ float  g_qv[QTOT];             // per-query clamped chamfer value
__device__ int    g_queue[QTOT];          // straggler query ids
__device__ int    g_nstrag;               // zero-init; reset each run
__device__ float  g_rpart[RBLOCKS];
__device__ int    g_count;                // zero-init; reset each run

__device__ __forceinline__ int bucketOf(float x) {
    int bk = (int)floorf((x - XMIN) * INVW);
    return min(max(bk, 0), NB - 1);       // clamp keeps end-buckets conservative
}

// ---------------- Pass 0: transform + pack + counting-sort by x-bucket ----------
__global__ void __launch_bounds__(PTH)
prep_kernel(const float* __restrict__ X, const float* __restrict__ TV,
            const float* __restrict__ TR) {
    extern __shared__ char smraw[];
    float4* s   = (float4*)smraw;
    int*    cnt = (int*)(s + NPTS);
    int*    off = cnt + NB;

    int bid = blockIdx.x;
    int b   = bid & (B_ - 1);
    int c   = bid >> 4;
    int tid = threadIdx.x;

    const float* Tm = TR + 16 * b;
    float T00 = __ldg(Tm + 0),  T01 = __ldg(Tm + 1),  T02 = __ldg(Tm + 2),  T03 = __ldg(Tm + 3);
    float T10 = __ldg(Tm + 4),  T11 = __ldg(Tm + 5),  T12 = __ldg(Tm + 6),  T13 = __ldg(Tm + 7);
    float T20 = __ldg(Tm + 8),  T21 = __ldg(Tm + 9),  T22 = __ldg(Tm + 10), T23 = __ldg(Tm + 11);
    float T30 = __ldg(Tm + 12), T31 = __ldg(Tm + 13), T32 = __ldg(Tm + 14), T33 = __ldg(Tm + 15);

    if (tid < NB) cnt[tid] = 0;
    __syncthreads();

    const float* src = (c == 0 ? X : TV) + (size_t)b * NPTS * 3;
#pragma unroll
    for (int i = tid; i < NPTS; i += PTH) {
        const float* p = src + 3 * i;
        float x = p[0], y = p[1], z = p[2];
        if (c == 1) {
            float u0 = x * T00 + y * T10 + z * T20 + T30;
            float u1 = x * T01 + y * T11 + z * T21 + T31;
            float u2 = x * T02 + y * T12 + z * T22 + T32;
            float w  = x * T03 + y * T13 + z * T23 + T33;
            float inv = 1.0f / w;
            x = u0 * inv; y = u1 * inv; z = u2 * inv;
        }
        s[i] = make_float4(x, y, z, 0.5f * (x * x + y * y + z * z));
        atomicAdd(&cnt[bucketOf(x)], 1);
    }
    __syncthreads();

    if (tid < NB) off[tid + 1] = cnt[tid];
    if (tid == 0) off[0] = 0;
    __syncthreads();
#pragma unroll
    for (int st = 1; st < NB; st <<= 1) {
        int v = 0;
        if (tid < NB) {
            v = off[tid + 1];
            if (tid >= st) v += off[tid + 1 - st];
        }
        __syncthreads();
        if (tid < NB) off[tid + 1] = v;
        __syncthreads();
    }
    if (tid < NB) cnt[tid] = 0;
    __syncthreads();

#pragma unroll
    for (int i = tid; i < NPTS; i += PTH) {
        float4 p = s[i];
        int bk = bucketOf(p.x);
        int pos = off[bk] + atomicAdd(&cnt[bk], 1);
        g_db[c][b][pos] = p;
    }
    for (int i = tid; i <= NB; i += PTH) g_off[c][b][i] = off[i];
}

// ---------------- Pass 1: fixed-window scan + certification + enqueue ----------
// Warp = 64 consecutive (bucket-ordered) queries, 2/lane. Flat warp-uniform scan
// of CSR range [off[wlo], off[whi+1]) from global (L2/L1). u = 0.5|p|^2 - q.p;
// d = 2*(qw+u). Query certified iff window-edge bound 0.5*dx^2 - qw >= ub on
// both sides (or side clipped to array end). Uncertified -> queue.
__global__ void __launch_bounds__(P1TH)
pass1_kernel() {
    int gt   = blockIdx.x * P1TH + threadIdx.x;
    int lane = threadIdx.x & 31;
    int gq0  = gt * 2;                    // warp covers 64 consecutive queries
    int idx  = gq0 & (NPTS - 1);
    int cb   = gq0 >> 12;
    int b    = cb & (B_ - 1);
    int dir  = cb >> 4;

    const float4* Q   = g_db[dir][b];
    const float4* D   = g_db[1 - dir][b];
    const int*    off = g_off[1 - dir][b];

    float4 q0 = __ldg(&Q[idx]);
    float4 q1 = __ldg(&Q[idx + 1]);
    float nx0 = -q0.x, ny0 = -q0.y, nz0 = -q0.z, qw0 = q0.w;
    float nx1 = -q1.x, ny1 = -q1.y, nz1 = -q1.z, qw1 = q1.w;

    int b0 = bucketOf(q0.x), b1 = bucketOf(q1.x);
    int bmin = min(b0, b1), bmax = max(b0, b1);
#pragma unroll
    for (int o = 16; o; o >>= 1) {
        bmin = min(bmin, __shfl_xor_sync(0xffffffffu, bmin, o));
        bmax = max(bmax, __shfl_xor_sync(0xffffffffu, bmax, o));
    }
    int wlo = max(bmin - W, 0);
    int whi = min(bmax + W, NB - 1);
    int s = __ldg(&off[wlo]);
    int e = __ldg(&off[whi + 1]);

    float ub0 = 1e30f, ub1 = 1e30f;
    int i = s;
#pragma unroll 1
    for (; i + 2 <= e; i += 2) {
        float4 pa = __ldg(&D[i]);
        float4 pb = __ldg(&D[i + 1]);
        float ta0 = fmaf(pa.x, nx0, fmaf(pa.y, ny0, fmaf(pa.z, nz0, pa.w)));
        float ta1 = fmaf(pa.x, nx1, fmaf(pa.y, ny1, fmaf(pa.z, nz1, pa.w)));
        float tb0 = fmaf(pb.x, nx0, fmaf(pb.y, ny0, fmaf(pb.z, nz0, pb.w)));
        float tb1 = fmaf(pb.x, nx1, fmaf(pb.y, ny1, fmaf(pb.z, nz1, pb.w)));
        ub0 = fminf(ub0, fminf(ta0, tb0));
        ub1 = fminf(ub1, fminf(ta1, tb1));
    }
    if (i < e) {
        float4 pa = __ldg(&D[i]);
        ub0 = fminf(ub0, fmaf(pa.x, nx0, fmaf(pa.y, ny0, fmaf(pa.z, nz0, pa.w))));
        ub1 = fminf(ub1, fmaf(pa.x, nx1, fmaf(pa.y, ny1, fmaf(pa.z, nz1, pa.w))));
    }

    // certification against window edges
    float elo = XMIN + (float)wlo * BW;
    float ehi = XMIN + (float)(whi + 1) * BW;
    float dlo0 = q0.x - elo, dhi0 = ehi - q0.x;
    float dlo1 = q1.x - elo, dhi1 = ehi - q1.x;
    bool c0 = ((wlo == 0)      || (fmaf(0.5f * dlo0, dlo0, -qw0) >= ub0)) &&
              ((whi == NB - 1) || (fmaf(0.5f * dhi0, dhi0, -qw0) >= ub0));
    bool c1 = ((wlo == 0)      || (fmaf(0.5f * dlo1, dlo1, -qw1) >= ub1)) &&
              ((whi == NB - 1) || (fmaf(0.5f * dhi1, dhi1, -qw1) >= ub1));

    g_qv[gq0]     = fmaxf(2.0f * (qw0 + ub0), 0.0f);
    g_qv[gq0 + 1] = fmaxf(2.0f * (qw1 + ub1), 0.0f);

    // ballot-compact uncertified queries into the global queue
    unsigned m0 = __ballot_sync(0xffffffffu, !c0);
    unsigned m1 = __ballot_sync(0xffffffffu, !c1);
    int n0 = __popc(m0), n1 = __popc(m1);
    int base = 0;
    if (lane == 0 && (n0 + n1)) base = atomicAdd(&g_nstrag, n0 + n1);
    base = __shfl_sync(0xffffffffu, base, 0);
    unsigned mlt = (1u << lane) - 1u;
    if (!c0) g_queue[base + __popc(m0 & mlt)]      = gq0;
    if (!c1) g_queue[base + n0 + __popc(m1 & mlt)] = gq0 + 1;
}

// ---------------- Pass 2: stragglers — one query per WARP ----------------
// Slab radius r = sqrt(val) from pass 1's upper bound provably contains the NN.
// 32 lanes stride the slab's CSR range; warp-reduce min; overwrite g_qv slot.
__global__ void __launch_bounds__(SGTH)
straggler_kernel() {
    int warpsTotal = SGBLOCKS * (SGTH / 32);
    int wid  = (blockIdx.x * SGTH + threadIdx.x) >> 5;
    int lane = threadIdx.x & 31;
    int n = g_nstrag;

#pragma unroll 1
    for (int t = wid; t < n; t += warpsTotal) {
        int gq  = g_queue[t];
        int idx = gq & (NPTS - 1);
        int cb  = gq >> 12;
        int b   = cb & (B_ - 1);
        int dir = cb >> 4;

        const float4* D   = g_db[1 - dir][b];
        const int*    off = g_off[1 - dir][b];
        float4 q = __ldg(&g_db[dir][b][idx]);
        float nx = -q.x, ny = -q.y, nz = -q.z, qw = q.w;

        float val = g_qv[gq];
        float r = sqrtf(val) * 1.0002f + 1e-6f;
        int lo = bucketOf(q.x - r);
        int hi = bucketOf(q.x + r);
        int s = __ldg(&off[lo]);
        int e = __ldg(&off[hi + 1]);

        float ub = 1e30f;
#pragma unroll 1
        for (int i = s + lane; i < e; i += 32) {
            float4 p = __ldg(&D[i]);
            float u = fmaf(p.x, nx, fmaf(p.y, ny, fmaf(p.z, nz, p.w)));
            ub = fminf(ub, u);
        }
#pragma unroll
        for (int o = 16; o; o >>= 1)
            ub = fminf(ub, __shfl_xor_sync(0xffffffffu, ub, o));
        if (lane == 0)
            g_qv[gq] = fmaxf(2.0f * (qw + ub), 0.0f);
    }
}

// ---------------- Pass 3: deterministic fixed-order reduce ----------------
__global__ void __launch_bounds__(RTH)
reduce_kernel(float* __restrict__ out) {
    __shared__ float red[RTH];
    __shared__ bool isLast;
    int t = threadIdx.x;
    const float4* V = (const float4*)g_qv;
    float4 v = V[blockIdx.x * RTH + t];
    red[t] = (v.x + v.y) + (v.z + v.w);
    __syncthreads();
#pragma unroll
    for (int off = RTH / 2; off > 0; off >>= 1) {
        if (t < off) red[t] += red[t + off];
        __syncthreads();
    }
    if (t == 0) {
        g_rpart[blockIdx.x] = red[0];
        __threadfence();
        int prev = atomicAdd(&g_count, 1);
        isLast = (prev == RBLOCKS - 1);
    }
    __syncthreads();

    if (isLast) {
        red[t] = (t < RBLOCKS) ? g_rpart[t] : 0.0f;
        __syncthreads();
#pragma unroll
        for (int off = RTH / 2; off > 0; off >>= 1) {
            if (t < off) red[t] += red[t + off];
            __syncthreads();
        }
        if (t == 0) {
            out[0] = red[0];
            g_count = 0;       // reset counters for graph replay determinism
            g_nstrag = 0;
        }
    }
}

extern "C" void kernel_launch(void* const* d_in, const int* in_sizes, int n_in,
                              void* d_out, int out_size) {
    const float* X  = (const float*)d_in[0];  // [16,4096,3]
    const float* TV = (const float*)d_in[1];  // [16,4096,3]
    const float* TR = (const float*)d_in[2];  // [16,4,4]
    float* out = (float*)d_out;

    cudaFuncSetAttribute(prep_kernel,
                         cudaFuncAttributeMaxDynamicSharedMemorySize, SMEM_PREP);

    prep_kernel<<<2 * B_, PTH, SMEM_PREP>>>(X, TV, TR);
    pass1_kernel<<<P1BLOCKS, P1TH>>>();
    straggler_kernel<<<SGBLOCKS, SGTH>>>();
    reduce_kernel<<<RBLOCKS, RTH>>>(out);
}